// round 17
// baseline (speedup 1.0000x reference)
#include <cuda_runtime.h>
#include <cstdint>

#define DDEPTH 8
#define HDIM   4096
#define NT     1024
#define NWARP  (NT / 32)    // 32
#define HPT    4            // hidden dims per thread (1024*4 = 4096)
#define EPSV   1e-6f
#define STAGES 6            // TMA ring, pair-granular: site=4 stages + 2 slack
#define ROW_BYTES  (HDIM * 4)        // 16 KiB
#define PAIR_BYTES (2 * ROW_BYTES)   // 32 KiB

#define DOT4(a,b) ((a).x*(b).x + (a).y*(b).y + (a).z*(b).z + (a).w*(b).w)

__device__ __forceinline__ uint32_t smem_u32(const void* p) {
    uint32_t a;
    asm("{ .reg .u64 t; cvta.to.shared.u64 t, %1; cvt.u32.u64 %0, t; }"
        : "=r"(a) : "l"(p));
    return a;
}
__device__ __forceinline__ void mbar_init(uint32_t mb, uint32_t cnt) {
    asm volatile("mbarrier.init.shared.b64 [%0], %1;" :: "r"(mb), "r"(cnt) : "memory");
}
__device__ __forceinline__ void mbar_expect_tx(uint32_t mb, uint32_t bytes) {
    asm volatile("mbarrier.arrive.expect_tx.shared.b64 _, [%0], %1;"
                 :: "r"(mb), "r"(bytes) : "memory");
}
__device__ __forceinline__ void mbar_arrive(uint32_t mb) {
    asm volatile("mbarrier.arrive.shared.b64 _, [%0];" :: "r"(mb) : "memory");
}
__device__ __forceinline__ void mbar_wait(uint32_t mb, uint32_t parity) {
    uint32_t done;
    asm volatile(
        "{ .reg .pred p;"
        "  mbarrier.try_wait.parity.acquire.cta.shared::cta.b64 p, [%1], %2;"
        "  selp.b32 %0, 1, 0, p; }"
        : "=r"(done) : "r"(mb), "r"(parity) : "memory");
    if (!done) {
        asm volatile(
            "{ .reg .pred P1;"
            "WAIT_LOOP_%=:"
            "  mbarrier.try_wait.parity.acquire.cta.shared::cta.b64 P1, [%0], %1, 0x989680;"
            "  @P1 bra.uni WAIT_DONE_%=;"
            "  bra.uni WAIT_LOOP_%=;"
            "WAIT_DONE_%=: }"
            :: "r"(mb), "r"(parity) : "memory");
    }
}
__device__ __forceinline__ void bulk_cp(uint32_t sdst, const float* gsrc,
                                        uint32_t bytes, uint32_t mb) {
    asm volatile(
        "cp.async.bulk.shared::cluster.global.mbarrier::complete_tx::bytes "
        "[%0], [%1], %2, [%3];"
        :: "r"(sdst), "l"(gsrc), "r"(bytes), "r"(mb) : "memory");
}

// Persistent 1 CTA/SM, 1024 threads. TMA ring of 6 pair-stages (192 KiB).
// Per site: pass1 streams 4 pairs computing 16 scalar partials (no barriers),
// ONE block reduction, softmax once, combine RE-READS the ring, then stages
// are freed. Serial overhead paid once per site instead of 4x.
__global__ __launch_bounds__(NT, 1)
void fullattnres_kernel(const float* __restrict__ values,
                        const float* __restrict__ query,
                        const float* __restrict__ weight,
                        float* __restrict__ out,
                        int SB)
{
    extern __shared__ float sbuf[];        // [STAGES][2][HDIM] (192 KiB)
    __shared__ float red[NWARP][20];       // 16 scalars/warp, padded row (80 B)
    __shared__ float fin[16];              // [0..7]=ss totals, [8..15]=dp totals
    __shared__ unsigned long long full_b[STAGES], empty_b[STAGES];

    const int tid  = threadIdx.x;
    const int lane = tid & 31;
    const int warp = tid >> 5;
    const int h    = tid * HPT;
    const int grid = gridDim.x;
    const size_t dstr = (size_t)SB * HDIM;

    if ((int)blockIdx.x >= SB) return;
    const int nsites = (SB - 1 - (int)blockIdx.x) / grid + 1;
    const int npairs = nsites * 4;

    uint32_t full_a[STAGES], empty_a[STAGES];
    #pragma unroll
    for (int i = 0; i < STAGES; i++) {
        full_a[i]  = smem_u32(&full_b[i]);
        empty_a[i] = smem_u32(&empty_b[i]);
    }
    if (tid == 0) {
        #pragma unroll
        for (int i = 0; i < STAGES; i++) { mbar_init(full_a[i], 1); mbar_init(empty_a[i], 1); }
    }
    __syncthreads();

    // fused q*w for this thread's 4 dims (once per persistent CTA)
    const float4 q0 = *(const float4*)(query + h);
    const float4 w0 = *(const float4*)(weight + h);
    const float4 qw = make_float4(q0.x*w0.x, q0.y*w0.y, q0.z*w0.z, q0.w*w0.w);

    const uint32_t sbase = smem_u32(sbuf);

    int p_stage = 0, p_phase = 1;   // producer cursor (tid0); R14-validated protocol
    int c_stage = 0, c_phase = 0;   // consumer cursor
    int next_g  = 0;

    auto issue_pair = [&](int g) {   // tid==0 only
        mbar_wait(empty_a[p_stage], (uint32_t)p_phase);
        const int psite = (int)blockIdx.x + (g >> 2) * grid;
        const int ppr   = g & 3;
        const float* gb = values + (size_t)psite * HDIM + (size_t)(2 * ppr) * dstr;
        const uint32_t sd = sbase + (uint32_t)p_stage * PAIR_BYTES;
        mbar_expect_tx(full_a[p_stage], PAIR_BYTES);
        bulk_cp(sd,             gb,        ROW_BYTES, full_a[p_stage]);
        bulk_cp(sd + ROW_BYTES, gb + dstr, ROW_BYTES, full_a[p_stage]);
        if (++p_stage == STAGES) { p_stage = 0; p_phase ^= 1; }
    };

    // prologue: fill the whole ring (6 pairs = 1.5 sites in flight)
    if (tid == 0) {
        for (int g = 0; g < STAGES && g < npairs; g++) issue_pair(g);
        next_g = (STAGES < npairs) ? STAGES : npairs;
    }

    for (int si = 0; si < nsites; si++) {
        const int site = (int)blockIdx.x + si * grid;

        // ── pass 1: stream 4 pairs from the ring, 16 scalar partials,
        //    NO barriers, NO shuffles, stages NOT freed yet ──
        float ss[DDEPTH], dp[DDEPTH];
        int st[4];
        #pragma unroll
        for (int pr = 0; pr < 4; pr++) {
            st[pr] = c_stage;
            mbar_wait(full_a[c_stage], (uint32_t)c_phase);
            const float* cb = sbuf + c_stage * 2 * HDIM + h;
            const float4 va = *(const float4*)(cb);
            const float4 vb = *(const float4*)(cb + HDIM);
            ss[2*pr]     = DOT4(va, va);
            dp[2*pr]     = DOT4(qw, va);
            ss[2*pr + 1] = DOT4(vb, vb);
            dp[2*pr + 1] = DOT4(qw, vb);
            if (++c_stage == STAGES) { c_stage = 0; c_phase ^= 1; }
        }

        // ── ONE block reduction of 16 scalars ──
        #pragma unroll
        for (int off = 16; off > 0; off >>= 1) {
            #pragma unroll
            for (int d = 0; d < DDEPTH; d++) {
                ss[d] += __shfl_xor_sync(0xFFFFFFFFu, ss[d], off);
                dp[d] += __shfl_xor_sync(0xFFFFFFFFu, dp[d], off);
            }
        }
        if (lane == 0) {
            *(float4*)&red[warp][0]  = make_float4(ss[0], ss[1], ss[2], ss[3]);
            *(float4*)&red[warp][4]  = make_float4(ss[4], ss[5], ss[6], ss[7]);
            *(float4*)&red[warp][8]  = make_float4(dp[0], dp[1], dp[2], dp[3]);
            *(float4*)&red[warp][12] = make_float4(dp[4], dp[5], dp[6], dp[7]);
        }
        __syncthreads();

        // cross-warp: warp w (<16) reduces scalar w over the 32 warp partials
        if (warp < 16) {
            float t = red[lane][warp];
            #pragma unroll
            for (int off = 16; off > 0; off >>= 1)
                t += __shfl_xor_sync(0xFFFFFFFFu, t, off);
            if (lane == 0) fin[warp] = t;
        }
        __syncthreads();

        // ── softmax over depth (redundant per thread; broadcast LDS) ──
        const float4 fs0 = *(const float4*)&fin[0];
        const float4 fs1 = *(const float4*)&fin[4];
        const float4 fd0 = *(const float4*)&fin[8];
        const float4 fd1 = *(const float4*)&fin[12];
        float wt[DDEPTH];
        wt[0] = fd0.x * rsqrtf(fs0.x * (1.0f/HDIM) + EPSV);
        wt[1] = fd0.y * rsqrtf(fs0.y * (1.0f/HDIM) + EPSV);
        wt[2] = fd0.z * rsqrtf(fs0.z * (1.0f/HDIM) + EPSV);
        wt[3] = fd0.w * rsqrtf(fs0.w * (1.0f/HDIM) + EPSV);
        wt[4] = fd1.x * rsqrtf(fs1.x * (1.0f/HDIM) + EPSV);
        wt[5] = fd1.y * rsqrtf(fs1.y * (1.0f/HDIM) + EPSV);
        wt[6] = fd1.z * rsqrtf(fs1.z * (1.0f/HDIM) + EPSV);
        wt[7] = fd1.w * rsqrtf(fs1.w * (1.0f/HDIM) + EPSV);
        float mx = wt[0];
        #pragma unroll
        for (int d = 1; d < DDEPTH; d++) mx = fmaxf(mx, wt[d]);
        float sum = 0.f;
        #pragma unroll
        for (int d = 0; d < DDEPTH; d++) { wt[d] = __expf(wt[d] - mx); sum += wt[d]; }
        const float inv = 1.0f / sum;

        // ── combine: RE-READ the 8 rows from the ring (smem, zero DRAM) ──
        float4 o = make_float4(0.f, 0.f, 0.f, 0.f);
        #pragma unroll
        for (int d = 0; d < DDEPTH; d++) {
            const float* rp = sbuf + st[d >> 1] * 2 * HDIM + (d & 1) * HDIM + h;
            const float4 v = *(const float4*)rp;
            const float wd = wt[d] * inv;
            o.x += wd * v.x;  o.y += wd * v.y;
            o.z += wd * v.z;  o.w += wd * v.w;
        }
        *(float4*)(out + (size_t)site * HDIM + h) = o;

        __syncthreads();   // all combine reads done -> stages can be freed
        if (tid == 0) {
            #pragma unroll
            for (int k = 0; k < 4; k++) mbar_arrive(empty_a[st[k]]);
            // refill: pair 4si+6+k reuses exactly the stage freed by pair 4si+k,
            // so these empty-waits always hit the fast path
            #pragma unroll
            for (int k = 0; k < 4; k++)
                if (next_g < npairs) issue_pair(next_g++);
        }
    }
}

extern "C" void kernel_launch(void* const* d_in, const int* in_sizes, int n_in,
                              void* d_out, int out_size)
{
    const float* values = (const float*)d_in[0];  // [D,S,B,H]
    const float* query  = (const float*)d_in[1];  // [H]
    const float* weight = (const float*)d_in[2];  // [H]
    float* out = (float*)d_out;                   // [S,B,H]

    const int H  = in_sizes[1];                   // 4096
    const int SB = out_size / H;                  // S*B = 4096

    const size_t smem_bytes = (size_t)STAGES * PAIR_BYTES;  // 192 KiB
    cudaFuncSetAttribute(fullattnres_kernel,
                         cudaFuncAttributeMaxDynamicSharedMemorySize,
                         (int)smem_bytes);

    int sms = 148;
    cudaDeviceGetAttribute(&sms, cudaDevAttrMultiProcessorCount, 0);
    int grid = sms;                               // persistent: 1 CTA per SM
    if (grid > SB) grid = SB;

    fullattnres_kernel<<<grid, NT, smem_bytes>>>(values, query, weight, out, SB);
}